// round 10
// baseline (speedup 1.0000x reference)
#include <cuda_runtime.h>

#define B_    32
#define N_    8192
#define HD    256     // H_DIM
#define GH    512     // G_HID
#define GD    256     // G_DIM
#define KC    64      // K
#define CHUNK 128     // N_/KC
#define ROWS  129     // 2K+1
#define M_TOT 4128    // B_*ROWS

typedef unsigned long long u64;

// Scratch (static device globals — no allocation allowed)
__device__ float d_H [M_TOT * HD];   // 4.2 MB
__device__ float d_h1[M_TOT * GH];   // 8.4 MB
__device__ float d_gs[M_TOT * GD];   // 4.2 MB
__device__ float d_Sp[4 * B_ * GD];

// ---------------------------------------------------------------------------
// packed f32x2 helpers (FFMA2 is PTX-only; ptxas never auto-fuses)
// ---------------------------------------------------------------------------
__device__ __forceinline__ u64 dup2(float x) {
    unsigned xi = __float_as_uint(x);
    u64 r;
    asm("mov.b64 %0, {%1, %1};" : "=l"(r) : "r"(xi));
    return r;
}
__device__ __forceinline__ void ffma2(u64& d, u64 a, u64 b) {
    asm("fma.rn.f32x2 %0, %1, %2, %0;" : "+l"(d) : "l"(a), "l"(b));
}
__device__ __forceinline__ float2 unpk(u64 v) {
    unsigned lo, hi;
    asm("mov.b64 {%0, %1}, %2;" : "=r"(lo), "=r"(hi) : "l"(v));
    return make_float2(__uint_as_float(lo), __uint_as_float(hi));
}

// ---------------------------------------------------------------------------
// Kernel 0: mask (placed first so idx3 of the launch sequence = gemm2)
// ---------------------------------------------------------------------------
__global__ void mask_kernel(float* __restrict__ out)
{
    float* mask = out + (size_t)B_ * (KC + 1) * GD;
    for (int i = threadIdx.x; i < B_ * (KC + 1); i += blockDim.x)
        mask[i] = 1.0f;
}

// ---------------------------------------------------------------------------
// Kernel 1: clustered reduction. Grid (K, B), 512 threads (8 row-groups).
// cs staged to smem; hs float4 loads unconditional (front-batched, MLP=16);
// predicate applies only to the adds.
// ---------------------------------------------------------------------------
__global__ __launch_bounds__(512)
void reduce_kernel(const float* __restrict__ hs,
                   const int*   __restrict__ cs,
                   const int*   __restrict__ n_ptr)
{
    const int k    = blockIdx.x;
    const int b    = blockIdx.y;
    const int tid  = threadIdx.x;
    const int lane = tid & 63;    // h/4
    const int grp  = tid >> 6;    // 0..7
    const int base = k * CHUNK;

    __shared__ int    scs[CHUNK];
    __shared__ int    sn;
    __shared__ float4 sm[8][64];

    if (tid < CHUNK) scs[tid] = cs[base + tid];
    if (tid == 0)    sn = *n_ptr;
    __syncthreads();

    const int n = sn;
    const float* p = hs + ((size_t)b * N_ + base) * HD + lane * 4;

    float4 s = make_float4(0.f, 0.f, 0.f, 0.f);
#pragma unroll 16
    for (int i = grp; i < CHUNK; i += 8) {
        float4 v = *(const float4*)(p + (size_t)i * HD);   // always in-bounds
        if (((base + i) < n) & (scs[i] == k)) {
            s.x += v.x; s.y += v.y; s.z += v.z; s.w += v.w;
        }
    }
    sm[grp][lane] = s;
    __syncthreads();

    if (grp == 0) {
        float4 t = sm[0][lane];
#pragma unroll
        for (int g = 1; g < 8; ++g) {
            float4 u = sm[g][lane];
            t.x += u.x; t.y += u.y; t.z += u.z; t.w += u.w;
        }
        float4 hv = *(const float4*)(hs + ((size_t)b * N_ + n) * HD + lane * 4);

        ((float4*)(d_H + (size_t)(b * ROWS + k)      * HD))[lane] = t;
        ((float4*)(d_H + (size_t)(b * ROWS + KC + k) * HD))[lane] =
            make_float4(t.x + hv.x, t.y + hv.y, t.z + hv.z, t.w + hv.w);
        if (k == 0)
            ((float4*)(d_H + (size_t)(b * ROWS + 2 * KC) * HD))[lane] = hv;
    }
}

// ---------------------------------------------------------------------------
// Kernels 2/3: fp32 GEMM, 128 x BN tile, BK=16, 256 threads, double-buffered
// smem with register prefetch, packed f32x2 accumulators.
// BN=128 -> 8x8 per thread; BN=64 -> 8x4 per thread.
// ---------------------------------------------------------------------------
template<int BN, bool RELU>
__global__ __launch_bounds__(256)
void gemm_kernel(const float* __restrict__ A,
                 const float* __restrict__ W,
                 const float* __restrict__ bias,
                 float* __restrict__ C,
                 int M, int Nn, int Ktot)
{
    constexpr int BM = 128, BK = 16;
    constexpr int TN  = BN / 16;
    constexpr int TN2 = TN / 2;
    constexpr int BV  = BN / 64;

    __shared__ float As[2][BK][BM + 4];
    __shared__ float Bs[2][BK][BN + 4];

    const int tid = threadIdx.x;
    const int tx  = tid & 15;
    const int ty  = tid >> 4;
    const int m0  = blockIdx.y * BM;
    const int n0  = blockIdx.x * BN;

    const int ar = tid >> 1;
    const int ac = (tid & 1) * 8;
    const bool a_ok = (m0 + ar) < M;
    const float* aptr = A + (size_t)(m0 + ar) * Ktot + ac;

    int brow[BV], bcol[BV];
#pragma unroll
    for (int t = 0; t < BV; ++t) {
        const int idx4 = tid + t * 256;
        brow[t] = idx4 / (BN / 4);
        bcol[t] = (idx4 % (BN / 4)) * 4;
    }

    u64 acc[8][TN2];
#pragma unroll
    for (int i = 0; i < 8; ++i)
#pragma unroll
        for (int j = 0; j < TN2; ++j) acc[i][j] = 0ull;

    float4 pa0 = make_float4(0,0,0,0), pa1 = pa0;
    float4 pb[BV];
    if (a_ok) { pa0 = *(const float4*)aptr; pa1 = *(const float4*)(aptr + 4); }
#pragma unroll
    for (int t = 0; t < BV; ++t)
        pb[t] = *(const float4*)(W + (size_t)brow[t] * Nn + n0 + bcol[t]);

    As[0][ac+0][ar] = pa0.x; As[0][ac+1][ar] = pa0.y;
    As[0][ac+2][ar] = pa0.z; As[0][ac+3][ar] = pa0.w;
    As[0][ac+4][ar] = pa1.x; As[0][ac+5][ar] = pa1.y;
    As[0][ac+6][ar] = pa1.z; As[0][ac+7][ar] = pa1.w;
#pragma unroll
    for (int t = 0; t < BV; ++t)
        *(float4*)&Bs[0][brow[t]][bcol[t]] = pb[t];
    __syncthreads();

    int buf = 0;
    for (int k0 = 0; k0 < Ktot; k0 += BK) {
        const int k1 = k0 + BK;
        const bool more = (k1 < Ktot);

        if (more) {
            if (a_ok) {
                pa0 = *(const float4*)(aptr + k1);
                pa1 = *(const float4*)(aptr + k1 + 4);
            }
#pragma unroll
            for (int t = 0; t < BV; ++t)
                pb[t] = *(const float4*)(W + (size_t)(k1 + brow[t]) * Nn + n0 + bcol[t]);
        }

#pragma unroll
        for (int kk = 0; kk < BK; ++kk) {
            float4 a0 = *(const float4*)&As[buf][kk][ty * 8];
            float4 a1 = *(const float4*)&As[buf][kk][ty * 8 + 4];
            const u64* bp = (const u64*)&Bs[buf][kk][tx * TN];
            u64 breg[TN2];
#pragma unroll
            for (int j = 0; j < TN2; ++j) breg[j] = bp[j];

            const float av[8] = {a0.x, a0.y, a0.z, a0.w, a1.x, a1.y, a1.z, a1.w};
#pragma unroll
            for (int i = 0; i < 8; ++i) {
                const u64 ad = dup2(av[i]);
#pragma unroll
                for (int j = 0; j < TN2; ++j) ffma2(acc[i][j], ad, breg[j]);
            }
        }

        if (more) {
            const int nb = buf ^ 1;
            As[nb][ac+0][ar] = pa0.x; As[nb][ac+1][ar] = pa0.y;
            As[nb][ac+2][ar] = pa0.z; As[nb][ac+3][ar] = pa0.w;
            As[nb][ac+4][ar] = pa1.x; As[nb][ac+5][ar] = pa1.y;
            As[nb][ac+6][ar] = pa1.z; As[nb][ac+7][ar] = pa1.w;
#pragma unroll
            for (int t = 0; t < BV; ++t)
                *(float4*)&Bs[nb][brow[t]][bcol[t]] = pb[t];
            __syncthreads();
            buf = nb;
        }
    }

    const int gn0 = n0 + tx * TN;
    float bsv[TN];
#pragma unroll
    for (int j = 0; j < TN; ++j) bsv[j] = bias[gn0 + j];

#pragma unroll
    for (int i = 0; i < 8; ++i) {
        const int gm = m0 + ty * 8 + i;
        if (gm >= M) continue;
        float o[TN];
#pragma unroll
        for (int j = 0; j < TN2; ++j) {
            float2 p = unpk(acc[i][j]);
            o[2*j]   = p.x + bsv[2*j];
            o[2*j+1] = p.y + bsv[2*j+1];
        }
        if (RELU) {
#pragma unroll
            for (int j = 0; j < TN; ++j) o[j] = fmaxf(o[j], 0.f);
        }
        float* cp = C + (size_t)gm * Nn + gn0;
#pragma unroll
        for (int j = 0; j < TN2; j += 2)
            *(float4*)(cp + j * 2) = make_float4(o[2*j], o[2*j+1], o[2*j+2], o[2*j+3]);
    }
}

// ---------------------------------------------------------------------------
// Kernel 4: partial S. Grid (4, B). Block (q,b) sums gs rows q*16..q*16+15.
// ---------------------------------------------------------------------------
__global__ void s_partial_kernel()
{
    const int q = blockIdx.x;
    const int b = blockIdx.y;
    const int h = threadIdx.x;
    const float* g = d_gs + (size_t)b * ROWS * GD;

    float s = 0.f;
#pragma unroll
    for (int j = q * 16; j < q * 16 + 16; ++j)
        s += g[(size_t)j * GD + h];
    d_Sp[((size_t)q * B_ + b) * GD + h] = s;
}

// ---------------------------------------------------------------------------
// Kernel 5: finalize. Grid (K+1, B), 256 threads.
// ---------------------------------------------------------------------------
__global__ void finalize_kernel(float* __restrict__ out)
{
    const int k = blockIdx.x;     // 0..K
    const int b = blockIdx.y;
    const int h = threadIdx.x;

    float S = d_Sp[((size_t)0 * B_ + b) * GD + h]
            + d_Sp[((size_t)1 * B_ + b) * GD + h]
            + d_Sp[((size_t)2 * B_ + b) * GD + h]
            + d_Sp[((size_t)3 * B_ + b) * GD + h];

    const float* g = d_gs + (size_t)b * ROWS * GD;

    float v;
    if (k < KC)
        v = S - g[(size_t)k * GD + h] + g[(size_t)(KC + k) * GD + h];
    else
        v = S + g[(size_t)(2 * KC) * GD + h];
    out[((size_t)b * (KC + 1) + k) * GD + h] = v;
}

// ---------------------------------------------------------------------------
extern "C" void kernel_launch(void* const* d_in, const int* in_sizes, int n_in,
                              void* d_out, int out_size)
{
    const float* hs = (const float*)d_in[0];
    const int*   cs = (const int*)  d_in[1];
    const float* W1 = (const float*)d_in[2];
    const float* b1 = (const float*)d_in[3];
    const float* W2 = (const float*)d_in[4];
    const float* b2 = (const float*)d_in[5];
    const int*   np = (const int*)  d_in[6];
    float* out = (float*)d_out;

    float *pH, *pH1, *pGS;
    cudaGetSymbolAddress((void**)&pH,  d_H);
    cudaGetSymbolAddress((void**)&pH1, d_h1);
    cudaGetSymbolAddress((void**)&pGS, d_gs);

    // idx0: mask
    mask_kernel<<<1, 256>>>(out);

    // idx1: clustered reduce + H materialization
    reduce_kernel<<<dim3(KC, B_), 512>>>(hs, cs, np);

    // idx2: layer 1 [4128,256]@[256,512]+b1, relu (128x128 tiles, 132 blocks)
    gemm_kernel<128, true ><<<dim3(GH / 128, (M_TOT + 127) / 128), 256>>>(pH,  W1, b1, pH1, M_TOT, GH, HD);

    // idx3: layer 2 [4128,512]@[512,256]+b2 (128x64 tiles, 132 blocks)  <- profiled slot
    gemm_kernel<64, false><<<dim3(GD / 64, (M_TOT + 127) / 128), 256>>>(pH1, W2, b2, pGS, M_TOT, GD, GH);

    // idx4: S partials
    s_partial_kernel<<<dim3(4, B_), 256>>>();

    // idx5: finalize
    finalize_kernel<<<dim3(KC + 1, B_), 256>>>(out);
}

// round 11
// speedup vs baseline: 1.0338x; 1.0338x over previous
#include <cuda_runtime.h>

#define B_    32
#define N_    8192
#define HD    256     // H_DIM
#define GH    512     // G_HID
#define GD    256     // G_DIM
#define KC    64      // K
#define CHUNK 128     // N_/KC
#define ROWS  129     // 2K+1
#define M_TOT 4128    // B_*ROWS

typedef unsigned long long u64;

// Scratch (static device globals — no allocation allowed)
__device__ float d_H [M_TOT * HD];   // 4.2 MB
__device__ float d_h1[M_TOT * GH];   // 8.4 MB
__device__ float d_gs[M_TOT * GD];   // 4.2 MB
__device__ float d_Sp[4 * B_ * GD];

// ---------------------------------------------------------------------------
// packed f32x2 helpers (FFMA2 is PTX-only; ptxas never auto-fuses)
// ---------------------------------------------------------------------------
__device__ __forceinline__ u64 dup2(float x) {
    unsigned xi = __float_as_uint(x);
    u64 r;
    asm("mov.b64 %0, {%1, %1};" : "=l"(r) : "r"(xi));
    return r;
}
__device__ __forceinline__ void ffma2(u64& d, u64 a, u64 b) {
    asm("fma.rn.f32x2 %0, %1, %2, %0;" : "+l"(d) : "l"(a), "l"(b));
}
__device__ __forceinline__ float2 unpk(u64 v) {
    unsigned lo, hi;
    asm("mov.b64 {%0, %1}, %2;" : "=r"(lo), "=r"(hi) : "l"(v));
    return make_float2(__uint_as_float(lo), __uint_as_float(hi));
}

// ---------------------------------------------------------------------------
// Kernel 0: mask (placed first so idx3 of the launch sequence = gemm2)
// ---------------------------------------------------------------------------
__global__ void mask_kernel(float* __restrict__ out)
{
    float* mask = out + (size_t)B_ * (KC + 1) * GD;
    for (int i = threadIdx.x; i < B_ * (KC + 1); i += blockDim.x)
        mask[i] = 1.0f;
}

// ---------------------------------------------------------------------------
// Kernel 1: clustered reduction. Grid (K, B), 512 threads (8 row-groups).
// cs staged to smem; hs float4 loads unconditional (front-batched, MLP=16);
// predicate applies only to the adds.
// ---------------------------------------------------------------------------
__global__ __launch_bounds__(512)
void reduce_kernel(const float* __restrict__ hs,
                   const int*   __restrict__ cs,
                   const int*   __restrict__ n_ptr)
{
    const int k    = blockIdx.x;
    const int b    = blockIdx.y;
    const int tid  = threadIdx.x;
    const int lane = tid & 63;    // h/4
    const int grp  = tid >> 6;    // 0..7
    const int base = k * CHUNK;

    __shared__ int    scs[CHUNK];
    __shared__ int    sn;
    __shared__ float4 sm[8][64];

    if (tid < CHUNK) scs[tid] = cs[base + tid];
    if (tid == 0)    sn = *n_ptr;
    __syncthreads();

    const int n = sn;
    const float* p = hs + ((size_t)b * N_ + base) * HD + lane * 4;

    float4 s = make_float4(0.f, 0.f, 0.f, 0.f);
#pragma unroll 16
    for (int i = grp; i < CHUNK; i += 8) {
        float4 v = *(const float4*)(p + (size_t)i * HD);   // always in-bounds
        if (((base + i) < n) & (scs[i] == k)) {
            s.x += v.x; s.y += v.y; s.z += v.z; s.w += v.w;
        }
    }
    sm[grp][lane] = s;
    __syncthreads();

    if (grp == 0) {
        float4 t = sm[0][lane];
#pragma unroll
        for (int g = 1; g < 8; ++g) {
            float4 u = sm[g][lane];
            t.x += u.x; t.y += u.y; t.z += u.z; t.w += u.w;
        }
        float4 hv = *(const float4*)(hs + ((size_t)b * N_ + n) * HD + lane * 4);

        ((float4*)(d_H + (size_t)(b * ROWS + k)      * HD))[lane] = t;
        ((float4*)(d_H + (size_t)(b * ROWS + KC + k) * HD))[lane] =
            make_float4(t.x + hv.x, t.y + hv.y, t.z + hv.z, t.w + hv.w);
        if (k == 0)
            ((float4*)(d_H + (size_t)(b * ROWS + 2 * KC) * HD))[lane] = hv;
    }
}

// ---------------------------------------------------------------------------
// Kernels 2/3: fp32 GEMM, 128 x BN tile, BK=16, 256 threads, double-buffered
// smem with register prefetch, packed f32x2 accumulators.
// BN=128 -> 8x8 per thread; BN=64 -> 8x4 per thread.
// ---------------------------------------------------------------------------
template<int BN, bool RELU>
__global__ __launch_bounds__(256)
void gemm_kernel(const float* __restrict__ A,
                 const float* __restrict__ W,
                 const float* __restrict__ bias,
                 float* __restrict__ C,
                 int M, int Nn, int Ktot)
{
    constexpr int BM = 128, BK = 16;
    constexpr int TN  = BN / 16;
    constexpr int TN2 = TN / 2;
    constexpr int BV  = BN / 64;

    __shared__ float As[2][BK][BM + 4];
    __shared__ float Bs[2][BK][BN + 4];

    const int tid = threadIdx.x;
    const int tx  = tid & 15;
    const int ty  = tid >> 4;
    const int m0  = blockIdx.y * BM;
    const int n0  = blockIdx.x * BN;

    const int ar = tid >> 1;
    const int ac = (tid & 1) * 8;
    const bool a_ok = (m0 + ar) < M;
    const float* aptr = A + (size_t)(m0 + ar) * Ktot + ac;

    int brow[BV], bcol[BV];
#pragma unroll
    for (int t = 0; t < BV; ++t) {
        const int idx4 = tid + t * 256;
        brow[t] = idx4 / (BN / 4);
        bcol[t] = (idx4 % (BN / 4)) * 4;
    }

    u64 acc[8][TN2];
#pragma unroll
    for (int i = 0; i < 8; ++i)
#pragma unroll
        for (int j = 0; j < TN2; ++j) acc[i][j] = 0ull;

    float4 pa0 = make_float4(0,0,0,0), pa1 = pa0;
    float4 pb[BV];
    if (a_ok) { pa0 = *(const float4*)aptr; pa1 = *(const float4*)(aptr + 4); }
#pragma unroll
    for (int t = 0; t < BV; ++t)
        pb[t] = *(const float4*)(W + (size_t)brow[t] * Nn + n0 + bcol[t]);

    As[0][ac+0][ar] = pa0.x; As[0][ac+1][ar] = pa0.y;
    As[0][ac+2][ar] = pa0.z; As[0][ac+3][ar] = pa0.w;
    As[0][ac+4][ar] = pa1.x; As[0][ac+5][ar] = pa1.y;
    As[0][ac+6][ar] = pa1.z; As[0][ac+7][ar] = pa1.w;
#pragma unroll
    for (int t = 0; t < BV; ++t)
        *(float4*)&Bs[0][brow[t]][bcol[t]] = pb[t];
    __syncthreads();

    int buf = 0;
    for (int k0 = 0; k0 < Ktot; k0 += BK) {
        const int k1 = k0 + BK;
        const bool more = (k1 < Ktot);

        if (more) {
            if (a_ok) {
                pa0 = *(const float4*)(aptr + k1);
                pa1 = *(const float4*)(aptr + k1 + 4);
            }
#pragma unroll
            for (int t = 0; t < BV; ++t)
                pb[t] = *(const float4*)(W + (size_t)(k1 + brow[t]) * Nn + n0 + bcol[t]);
        }

#pragma unroll
        for (int kk = 0; kk < BK; ++kk) {
            float4 a0 = *(const float4*)&As[buf][kk][ty * 8];
            float4 a1 = *(const float4*)&As[buf][kk][ty * 8 + 4];
            const u64* bp = (const u64*)&Bs[buf][kk][tx * TN];
            u64 breg[TN2];
#pragma unroll
            for (int j = 0; j < TN2; ++j) breg[j] = bp[j];

            const float av[8] = {a0.x, a0.y, a0.z, a0.w, a1.x, a1.y, a1.z, a1.w};
#pragma unroll
            for (int i = 0; i < 8; ++i) {
                const u64 ad = dup2(av[i]);
#pragma unroll
                for (int j = 0; j < TN2; ++j) ffma2(acc[i][j], ad, breg[j]);
            }
        }

        if (more) {
            const int nb = buf ^ 1;
            As[nb][ac+0][ar] = pa0.x; As[nb][ac+1][ar] = pa0.y;
            As[nb][ac+2][ar] = pa0.z; As[nb][ac+3][ar] = pa0.w;
            As[nb][ac+4][ar] = pa1.x; As[nb][ac+5][ar] = pa1.y;
            As[nb][ac+6][ar] = pa1.z; As[nb][ac+7][ar] = pa1.w;
#pragma unroll
            for (int t = 0; t < BV; ++t)
                *(float4*)&Bs[nb][brow[t]][bcol[t]] = pb[t];
            __syncthreads();
            buf = nb;
        }
    }

    const int gn0 = n0 + tx * TN;
    float bsv[TN];
#pragma unroll
    for (int j = 0; j < TN; ++j) bsv[j] = bias[gn0 + j];

#pragma unroll
    for (int i = 0; i < 8; ++i) {
        const int gm = m0 + ty * 8 + i;
        if (gm >= M) continue;
        float o[TN];
#pragma unroll
        for (int j = 0; j < TN2; ++j) {
            float2 p = unpk(acc[i][j]);
            o[2*j]   = p.x + bsv[2*j];
            o[2*j+1] = p.y + bsv[2*j+1];
        }
        if (RELU) {
#pragma unroll
            for (int j = 0; j < TN; ++j) o[j] = fmaxf(o[j], 0.f);
        }
        float* cp = C + (size_t)gm * Nn + gn0;
#pragma unroll
        for (int j = 0; j < TN2; j += 2)
            *(float4*)(cp + j * 2) = make_float4(o[2*j], o[2*j+1], o[2*j+2], o[2*j+3]);
    }
}

// ---------------------------------------------------------------------------
// Kernel 4: partial S. Grid (4, B). Block (q,b) sums gs rows q*16..q*16+15.
// ---------------------------------------------------------------------------
__global__ void s_partial_kernel()
{
    const int q = blockIdx.x;
    const int b = blockIdx.y;
    const int h = threadIdx.x;
    const float* g = d_gs + (size_t)b * ROWS * GD;

    float s = 0.f;
#pragma unroll
    for (int j = q * 16; j < q * 16 + 16; ++j)
        s += g[(size_t)j * GD + h];
    d_Sp[((size_t)q * B_ + b) * GD + h] = s;
}

// ---------------------------------------------------------------------------
// Kernel 5: finalize. Grid (K+1, B), 256 threads.
// ---------------------------------------------------------------------------
__global__ void finalize_kernel(float* __restrict__ out)
{
    const int k = blockIdx.x;     // 0..K
    const int b = blockIdx.y;
    const int h = threadIdx.x;

    float S = d_Sp[((size_t)0 * B_ + b) * GD + h]
            + d_Sp[((size_t)1 * B_ + b) * GD + h]
            + d_Sp[((size_t)2 * B_ + b) * GD + h]
            + d_Sp[((size_t)3 * B_ + b) * GD + h];

    const float* g = d_gs + (size_t)b * ROWS * GD;

    float v;
    if (k < KC)
        v = S - g[(size_t)k * GD + h] + g[(size_t)(KC + k) * GD + h];
    else
        v = S + g[(size_t)(2 * KC) * GD + h];
    out[((size_t)b * (KC + 1) + k) * GD + h] = v;
}

// ---------------------------------------------------------------------------
extern "C" void kernel_launch(void* const* d_in, const int* in_sizes, int n_in,
                              void* d_out, int out_size)
{
    const float* hs = (const float*)d_in[0];
    const int*   cs = (const int*)  d_in[1];
    const float* W1 = (const float*)d_in[2];
    const float* b1 = (const float*)d_in[3];
    const float* W2 = (const float*)d_in[4];
    const float* b2 = (const float*)d_in[5];
    const int*   np = (const int*)  d_in[6];
    float* out = (float*)d_out;

    float *pH, *pH1, *pGS;
    cudaGetSymbolAddress((void**)&pH,  d_H);
    cudaGetSymbolAddress((void**)&pH1, d_h1);
    cudaGetSymbolAddress((void**)&pGS, d_gs);

    // idx0: mask
    mask_kernel<<<1, 256>>>(out);

    // idx1: clustered reduce + H materialization
    reduce_kernel<<<dim3(KC, B_), 512>>>(hs, cs, np);

    // idx2: layer 1 [4128,256]@[256,512]+b1, relu (128x128 tiles, 132 blocks)
    gemm_kernel<128, true ><<<dim3(GH / 128, (M_TOT + 127) / 128), 256>>>(pH,  W1, b1, pH1, M_TOT, GH, HD);

    // idx3: layer 2 [4128,512]@[512,256]+b2 (128x64 tiles, 132 blocks)  <- profiled slot
    gemm_kernel<64, false><<<dim3(GD / 64, (M_TOT + 127) / 128), 256>>>(pH1, W2, b2, pGS, M_TOT, GD, GH);

    // idx4: S partials
    s_partial_kernel<<<dim3(4, B_), 256>>>();

    // idx5: finalize
    finalize_kernel<<<dim3(KC + 1, B_), 256>>>(out);
}